// round 14
// baseline (speedup 1.0000x reference)
#include <cuda_runtime.h>
#include <cuda_bf16.h>

#define THREADS 128
#define PAIRS 2
#define ROWS 16
#define XPITCH 132
#define SLOT (ROWS * XPITCH)
#define NBUF 2
#define MAXN (1 << 20)
#define MAXE (1 << 22)

__device__ int g_idx_is64;
__device__ int g_hist[MAXN];
__device__ int g_off[MAXN];
__device__ int g_se[MAXE];   // sorted edge ids
__device__ int g_sn[MAXE];   // node id per sorted position

static __device__ __forceinline__ unsigned int pack_bf16x2(float lo, float hi) {
    __nv_bfloat162 hh = __float22bfloat162_rn(make_float2(lo, hi));
    return *reinterpret_cast<unsigned int*>(&hh);
}
static __device__ __forceinline__ float2 unpack_bf16x2(unsigned int u) {
    float2 r;
    r.x = __uint_as_float(u << 16);
    r.y = __uint_as_float(u & 0xffff0000u);
    return r;
}

// ---------------- prep: zero out + zero hist + detect index dtype ----------------
__global__ void prep_kernel(float4* out, int n4, const unsigned int* idxw, int n_pairs, int nb) {
    int i = blockIdx.x * blockDim.x + threadIdx.x;
    int stride = gridDim.x * blockDim.x;
    for (int j = i; j < n4; j += stride) out[j] = make_float4(0.f, 0.f, 0.f, 0.f);
    for (int j = i; j < nb; j += stride) g_hist[j] = 0;
    if (blockIdx.x == 0) {
        __shared__ unsigned int acc;
        if (threadIdx.x == 0) acc = 0u;
        __syncthreads();
        unsigned int v = 0u;
        for (int j = threadIdx.x; j < n_pairs; j += blockDim.x) v |= idxw[2 * j + 1];
        atomicOr(&acc, v);
        __syncthreads();
        if (threadIdx.x == 0) g_idx_is64 = (acc == 0u) ? 1 : 0;
    }
}

// ---------------- pass 1: histogram ----------------
__global__ void hist_kernel(const int* __restrict__ idx, long long E) {
    const int is64 = g_idx_is64;
    long long i = blockIdx.x * (long long)blockDim.x + threadIdx.x;
    long long stride = gridDim.x * (long long)blockDim.x;
    for (long long e = i; e < E; e += stride) {
        int node = is64 ? idx[2 * e] : idx[e];
        atomicAdd(&g_hist[node], 1);
    }
}

// ---------------- pass 2: exclusive scan (single CTA) ----------------
__global__ void scan_kernel(int nb) {
    __shared__ int ssum[1024];
    const int t = threadIdx.x;
    const int chunk = (nb + 1023) / 1024;
    const int lo = t * chunk;
    const int hi = min(lo + chunk, nb);
    int s = 0;
    for (int i = lo; i < hi; i++) s += g_hist[i];
    ssum[t] = s;
    __syncthreads();
    for (int d = 1; d < 1024; d <<= 1) {
        int v = (t >= d) ? ssum[t - d] : 0;
        __syncthreads();
        ssum[t] += v;
        __syncthreads();
    }
    int run = (t > 0) ? ssum[t - 1] : 0;
    for (int i = lo; i < hi; i++) {
        int c = g_hist[i];
        g_off[i] = run;
        run += c;
    }
}

// ---------------- pass 3: rank scatter ----------------
__global__ void scatter_kernel(const int* __restrict__ idx, long long E) {
    const int is64 = g_idx_is64;
    long long i = blockIdx.x * (long long)blockDim.x + threadIdx.x;
    long long stride = gridDim.x * (long long)blockDim.x;
    for (long long e = i; e < E; e += stride) {
        int node = is64 ? idx[2 * e] : idx[e];
        int pos = atomicAdd(&g_off[node], 1);
        g_se[pos] = (int)e;
        g_sn[pos] = node;
    }
}

// ---------------- main: fused gate-GEMM + segmented v4 scatter ----------------
__global__ __launch_bounds__(THREADS, 4)
void fused_gate_scatter(const float* __restrict__ x,
                        const float* __restrict__ Wg,
                        const float* __restrict__ lparam,
                        float* __restrict__ out,
                        long long E, int num_tiles)
{
    extern __shared__ char smem_raw[];
    float* Xsm = reinterpret_cast<float*>(smem_raw);             // [PAIRS][NBUF][ROWS][XPITCH]
    int* NsmI = reinterpret_cast<int*>(Xsm + PAIRS * NBUF * SLOT); // [PAIRS][NBUF][ROWS]

    const int tid  = threadIdx.x;
    const int wid  = tid >> 5;
    const int lane = tid & 31;
    const int g    = lane >> 2;
    const int q    = lane & 3;
    const int pair = wid >> 1;
    const int h    = wid & 1;

    const float lp = fabsf(__ldg(lparam));

    float* pairBuf = Xsm + pair * (NBUF * SLOT);
    int* NsmP = NsmI + pair * (NBUF * ROWS);

    // ---- persistent B fragments ----
    unsigned int Breg[8][4][2];
    #pragma unroll
    for (int m = 0; m < 8; m++) {
        const int n = h * 64 + m * 8 + g;
        #pragma unroll
        for (int ks = 0; ks < 4; ks++) {
            const int k = ks * 16 + q * 2;
            float2 w0 = __ldg(reinterpret_cast<const float2*>(Wg + n * 64 + k));
            float2 w1 = __ldg(reinterpret_cast<const float2*>(Wg + n * 64 + k + 8));
            Breg[m][ks][0] = pack_bf16x2(w0.x, w0.y);
            Breg[m][ks][1] = pack_bf16x2(w1.x, w1.y);
        }
    }

    const unsigned int xbuf_u32 = (unsigned int)__cvta_generic_to_shared(pairBuf);
    const unsigned int nbuf_u32 = (unsigned int)__cvta_generic_to_shared(NsmP);

    // stage 16 sorted edges; warp h stages rows h*8..h*8+7 (x rows via id indirection)
    auto stage = [&](int t, int slot) {
        const long long ebase = (long long)t * ROWS;
        int myid = 0;
        {
            long long er = ebase + h * 8 + lane;
            if (lane < 8 && er < E) myid = g_se[er];
        }
        #pragma unroll
        for (int p = 0; p < 8; p++) {
            const int row = h * 8 + p;
            long long e = ebase + row;
            int id = __shfl_sync(0xffffffffu, myid, p);
            if (e < E) {
                unsigned int dst = xbuf_u32 + (unsigned)((slot * SLOT + row * XPITCH + lane * 4) * 4);
                const float* src = x + (long long)id * 128 + lane * 4;
                asm volatile("cp.async.cg.shared.global [%0], [%1], 16;" :: "r"(dst), "l"(src));
            }
        }
        if (h == 0 && lane < 4 && ebase + ROWS <= E) {
            unsigned int dst = nbuf_u32 + (unsigned)(slot * 64 + lane * 16);
            const char* src = (const char*)(g_sn + ebase) + lane * 16;
            asm volatile("cp.async.ca.shared.global [%0], [%1], 16;" :: "r"(dst), "l"(src));
        }
    };

    const int S  = (int)gridDim.x * PAIRS;
    const int pg = (int)blockIdx.x * PAIRS + pair;

    if (pg < num_tiles) stage(pg, 0);
    asm volatile("cp.async.commit_group;");

    int c = 0;
    for (int tcur = pg; tcur < num_tiles; tcur += S, c++) {
        asm volatile("cp.async.wait_group 0;");
        asm volatile("bar.sync %0, 64;" :: "r"(pair + 1) : "memory");
        int tpre = tcur + S;
        if (tpre < num_tiles) stage(tpre, (c + 1) & 1);
        asm volatile("cp.async.commit_group;");

        const int slot = c & 1;
        const long long tbase = (long long)tcur * ROWS;
        const bool fulltile = (tbase + ROWS <= E);

        #pragma unroll
        for (int sb = 0; sb < 2; sb++) {
            const int erow = sb * 8 + g;
            const long long eg = tbase + erow;
            const bool valid = (eg < E);
            const float* Xrow = pairBuf + slot * SLOT + erow * XPITCH;

            int nd = -1;
            if (valid)
                nd = fulltile ? NsmP[slot * ROWS + erow] : g_sn[eg];

            // segment structure across the 8 g-lanes (sorted => runs contiguous)
            int nd1 = __shfl_down_sync(0xffffffffu, nd, 4);
            int nd2 = __shfl_down_sync(0xffffffffu, nd, 8);
            int nd4 = __shfl_down_sync(0xffffffffu, nd, 16);
            int ndu = __shfl_up_sync(0xffffffffu, nd, 4);
            const bool ok0 = (g + 1 < 8) && (nd1 == nd) && (nd >= 0);
            const bool ok1 = (g + 2 < 8) && (nd2 == nd) && (nd >= 0);
            const bool ok2 = (g + 4 < 8) && (nd4 == nd) && (nd >= 0);
            const bool head = (nd >= 0) && (g == 0 || ndu != nd);

            // ---- load + convert A ----
            unsigned int ap0[4], ap1[4], ap2[4], ap3[4];
            float2 Fh_lo[4], Fh_hi[4];
            #pragma unroll
            for (int ks = 0; ks < 4; ks++) {
                const int kb = ks * 16 + q * 2;
                float2 f0 = *reinterpret_cast<const float2*>(Xrow + kb);
                float2 f1 = *reinterpret_cast<const float2*>(Xrow + 64 + kb);
                float2 f2 = *reinterpret_cast<const float2*>(Xrow + kb + 8);
                float2 f3 = *reinterpret_cast<const float2*>(Xrow + 64 + kb + 8);
                ap0[ks] = pack_bf16x2(f0.x, f0.y);
                ap1[ks] = pack_bf16x2(f1.x, f1.y);
                ap2[ks] = pack_bf16x2(f2.x, f2.y);
                ap3[ks] = pack_bf16x2(f3.x, f3.y);
                Fh_lo[ks] = h ? f1 : f0;
                Fh_hi[ks] = h ? f3 : f2;
            }

            float* nrow = out + (long long)nd * 128 + h * 64;

            #pragma unroll
            for (int pass = 0; pass < 2; pass++) {
                float acc[4][4];
                #pragma unroll
                for (int j = 0; j < 4; j++) {
                    acc[j][0] = 0.f; acc[j][1] = 0.f; acc[j][2] = 0.f; acc[j][3] = 0.f;
                }
                #pragma unroll
                for (int ks = 0; ks < 4; ks++) {
                    #pragma unroll
                    for (int j = 0; j < 4; j++) {
                        const int m = pass * 4 + j;
                        asm volatile(
                            "mma.sync.aligned.m16n8k16.row.col.f32.bf16.bf16.f32 "
                            "{%0,%1,%2,%3}, {%4,%5,%6,%7}, {%8,%9}, {%0,%1,%2,%3};"
                            : "+f"(acc[j][0]), "+f"(acc[j][1]),
                              "+f"(acc[j][2]), "+f"(acc[j][3])
                            : "r"(ap0[ks]), "r"(ap1[ks]), "r"(ap2[ks]), "r"(ap3[ks]),
                              "r"(Breg[m][ks][0]), "r"(Breg[m][ks][1]));
                    }
                }
                float2 V[4];
                #pragma unroll
                for (int j = 0; j < 4; j++) {
                    const int m  = pass * 4 + j;
                    const int ks = m >> 1;
                    float2 eh = (m & 1) ? Fh_hi[ks] : Fh_lo[ks];
                    unsigned int u0 = (m & 1) ? ap2[ks] : ap0[ks];
                    unsigned int u1 = (m & 1) ? ap3[ks] : ap1[ks];
                    float2 ge0 = h ? unpack_bf16x2(u0) : eh;
                    float2 ge1 = h ? eh : unpack_bf16x2(u1);
                    float sx = ge0.x * __saturatef(acc[j][0]) + ge1.x * __saturatef(acc[j][2]);
                    float sy = ge0.y * __saturatef(acc[j][1]) + ge1.y * __saturatef(acc[j][3]);
                    V[j].x = fmaf(lp, sx, eh.x);
                    V[j].y = fmaf(lp, sy, eh.y);
                }

                // ---- segmented reduction over g-lanes (same node -> accumulate) ----
                #pragma unroll
                for (int st = 0; st < 3; st++) {
                    const int d4 = 4 << st;
                    const bool ok = (st == 0) ? ok0 : (st == 1) ? ok1 : ok2;
                    #pragma unroll
                    for (int j = 0; j < 4; j++) {
                        float ox = __shfl_down_sync(0xffffffffu, V[j].x, d4);
                        float oy = __shfl_down_sync(0xffffffffu, V[j].y, d4);
                        if (ok) { V[j].x += ox; V[j].y += oy; }
                    }
                }

                // ---- quad-shuffle v4 packing; only segment heads scatter ----
                #pragma unroll
                for (int t2 = 0; t2 < 2; t2++) {
                    const int j0 = 2 * t2, j1 = 2 * t2 + 1;
                    float2 mine = (q & 1) ? V[j0] : V[j1];
                    float ox = __shfl_xor_sync(0xffffffffu, mine.x, 1);
                    float oy = __shfl_xor_sync(0xffffffffu, mine.y, 1);
                    float2 keep = (q & 1) ? V[j1] : V[j0];
                    float vx0 = (q & 1) ? ox : keep.x;
                    float vy0 = (q & 1) ? oy : keep.y;
                    float vx1 = (q & 1) ? keep.x : ox;
                    float vy1 = (q & 1) ? keep.y : oy;
                    const int mm = pass * 4 + j0 + (q & 1);
                    const int cb = mm * 8 + (q >> 1) * 4;
                    if (head) {
                        asm volatile("red.global.add.v4.f32 [%0], {%1,%2,%3,%4};"
                                     :: "l"(nrow + cb), "f"(vx0), "f"(vy0), "f"(vx1), "f"(vy1)
                                     : "memory");
                    }
                }
            }
        }
    }
}

// ---------------- launch ----------------
extern "C" void kernel_launch(void* const* d_in, const int* in_sizes, int n_in,
                              void* d_out, int out_size) {
    const float* x   = (const float*)d_in[0];
    const float* Wg  = (const float*)d_in[1];
    const float* lp  = (const float*)d_in[2];
    const int*   idx = (const int*)d_in[3];

    long long E = (long long)in_sizes[0] / 128;
    int nb = out_size / 128;              // dim_size
    int tiles = (int)((E + ROWS - 1) / ROWS);

    int dev = 0; cudaGetDevice(&dev);
    int sms = 148;
    cudaDeviceGetAttribute(&sms, cudaDevAttrMultiProcessorCount, dev);

    // prep: zero out + zero hist + detect index dtype
    int n4 = out_size / 4;
    long long npairs64 = E / 2; int npairs = npairs64 > 4096 ? 4096 : (int)npairs64;
    int zgrid = (n4 + 255) / 256;
    prep_kernel<<<zgrid, 256>>>((float4*)d_out, n4, (const unsigned int*)idx, npairs, nb);

    // counting sort by node
    int hgrid = (int)((E + 255) / 256); if (hgrid > 4096) hgrid = 4096;
    hist_kernel<<<hgrid, 256>>>(idx, E);
    scan_kernel<<<1, 1024>>>(nb);
    scatter_kernel<<<hgrid, 256>>>(idx, E);

    size_t smem = (size_t)PAIRS * NBUF * SLOT * 4 + (size_t)PAIRS * NBUF * ROWS * 4;
    cudaFuncSetAttribute(fused_gate_scatter,
                         cudaFuncAttributeMaxDynamicSharedMemorySize, (int)smem);
    int grid = 4 * sms;
    int maxg = (tiles + PAIRS - 1) / PAIRS;
    if (grid > maxg) grid = maxg;
    fused_gate_scatter<<<grid, THREADS, smem>>>(x, Wg, lp, (float*)d_out, E, tiles);
}

// round 15
// speedup vs baseline: 1.6678x; 1.6678x over previous
#include <cuda_runtime.h>
#include <cuda_bf16.h>

#define THREADS 128
#define PAIRS 2                       // warp pairs per CTA
#define ROWS 8                        // edges per pair-tile
#define XPITCH 132                    // fp32 words per staged edge row (4-bank pad)
#define SLOT (ROWS * XPITCH)          // floats per slot (1056)
#define NBUF 6                        // ring slots per pair (stage-ahead 5)

__device__ int g_idx_is64;

static __device__ __forceinline__ unsigned int pack_bf16x2(float lo, float hi) {
    __nv_bfloat162 hh = __float22bfloat162_rn(make_float2(lo, hi));
    return *reinterpret_cast<unsigned int*>(&hh);
}
static __device__ __forceinline__ float2 unpack_bf16x2(unsigned int u) {
    float2 r;
    r.x = __uint_as_float(u << 16);
    r.y = __uint_as_float(u & 0xffff0000u);
    return r;
}

// ---------------- prep: zero output + detect index dtype ----------------
__global__ void prep_kernel(float4* out, int n4, const unsigned int* idxw, int n_pairs) {
    int i = blockIdx.x * blockDim.x + threadIdx.x;
    int stride = gridDim.x * blockDim.x;
    for (; i < n4; i += stride) out[i] = make_float4(0.f, 0.f, 0.f, 0.f);
    if (blockIdx.x == 0) {
        __shared__ unsigned int acc;
        if (threadIdx.x == 0) acc = 0u;
        __syncthreads();
        unsigned int v = 0u;
        for (int j = threadIdx.x; j < n_pairs; j += blockDim.x) v |= idxw[2 * j + 1];
        atomicOr(&acc, v);
        __syncthreads();
        if (threadIdx.x == 0) g_idx_is64 = (acc == 0u) ? 1 : 0;
    }
}

// ---------------- fused gate-GEMM + v4 register scatter ----------------
__global__ __launch_bounds__(THREADS, 4)
void fused_gate_scatter(const float* __restrict__ x,
                        const float* __restrict__ Wg,
                        const float* __restrict__ lparam,
                        const void* __restrict__ index,
                        float* __restrict__ out,
                        long long E, int num_tiles)
{
    extern __shared__ char smem_raw[];
    float* Xsm = reinterpret_cast<float*>(smem_raw);                 // [PAIRS][NBUF][ROWS][XPITCH]
    long long* Nsm = reinterpret_cast<long long*>(Xsm + PAIRS * NBUF * SLOT); // [PAIRS][NBUF][ROWS]

    const int tid  = threadIdx.x;
    const int wid  = tid >> 5;
    const int lane = tid & 31;
    const int g    = lane >> 2;      // 0..7 : edge row within pair-tile
    const int q    = lane & 3;       // 0..3
    const int pair = wid >> 1;       // 0..1
    const int h    = wid & 1;        // 0/1 : gate-col half

    const int   is64 = g_idx_is64;
    const float lp   = fabsf(__ldg(lparam));

    float* pairBuf = Xsm + pair * (NBUF * SLOT);
    long long* NsmP = Nsm + pair * (NBUF * ROWS);
    int* NsmP32 = reinterpret_cast<int*>(NsmP);

    // ---- persistent B fragments: cols n = h*64 + m*8 + g, m = 0..7 ----
    unsigned int Breg[8][4][2];
    #pragma unroll
    for (int m = 0; m < 8; m++) {
        const int n = h * 64 + m * 8 + g;
        #pragma unroll
        for (int ks = 0; ks < 4; ks++) {
            const int k = ks * 16 + q * 2;
            float2 w0 = __ldg(reinterpret_cast<const float2*>(Wg + n * 64 + k));
            float2 w1 = __ldg(reinterpret_cast<const float2*>(Wg + n * 64 + k + 8));
            Breg[m][ks][0] = pack_bf16x2(w0.x, w0.y);
            Breg[m][ks][1] = pack_bf16x2(w1.x, w1.y);
        }
    }

    const unsigned int xbuf_u32 = (unsigned int)__cvta_generic_to_shared(pairBuf);
    const unsigned int nbuf_u32 = (unsigned int)__cvta_generic_to_shared(NsmP);

    // stage one 8-edge tile-let into slot; warp h stages rows h*4 .. h*4+3
    auto stage = [&](int t, int slot) {
        const long long ebase = (long long)t * ROWS;
        #pragma unroll
        for (int p = 0; p < 4; p++) {
            const int row = h * 4 + p;
            long long e = ebase + row;
            if (e < E) {
                unsigned int dst = xbuf_u32 + (unsigned)((slot * SLOT + row * XPITCH + lane * 4) * 4);
                const float* src = x + e * 128 + lane * 4;
                asm volatile("cp.async.cg.shared.global [%0], [%1], 16;" :: "r"(dst), "l"(src));
            }
        }
        // index staging only for full tiles; tail handled by direct LDG at consume
        if (h == 0 && ebase + ROWS <= E) {
            if (is64) {
                if (lane < 4) {
                    unsigned int dst = nbuf_u32 + (unsigned)(slot * 64 + lane * 16);
                    const char* src = (const char*)index + ebase * 8 + lane * 16;
                    asm volatile("cp.async.ca.shared.global [%0], [%1], 16;" :: "r"(dst), "l"(src));
                }
            } else {
                if (lane < 2) {
                    unsigned int dst = nbuf_u32 + (unsigned)(slot * 64 + lane * 16);
                    const char* src = (const char*)index + ebase * 4 + lane * 16;
                    asm volatile("cp.async.ca.shared.global [%0], [%1], 16;" :: "r"(dst), "l"(src));
                }
            }
        }
    };

    const int S  = (int)gridDim.x * PAIRS;
    const int pg = (int)blockIdx.x * PAIRS + pair;

    // ---- prologue: prime NBUF-1 slots ----
    #pragma unroll
    for (int j = 0; j < NBUF - 1; j++) {
        int t = pg + j * S;
        if (t < num_tiles) stage(t, j);
        asm volatile("cp.async.commit_group;");
    }

    int scur = 0;                        // slot of current tile (c % NBUF)
    for (int tcur = pg; tcur < num_tiles; tcur += S) {
        asm volatile("cp.async.wait_group %0;" :: "n"(NBUF - 2));     // own slot complete
        asm volatile("bar.sync %0, 64;" :: "r"(pair + 1) : "memory"); // partner done with restage target
        int tpre = tcur + (NBUF - 1) * S;
        const int spre = (scur == 0) ? (NBUF - 1) : (scur - 1);       // (scur+NBUF-1) mod NBUF
        if (tpre < num_tiles) stage(tpre, spre);
        asm volatile("cp.async.commit_group;");

        const int slot = scur;
        scur = (scur + 1 == NBUF) ? 0 : scur + 1;

        const long long ebase = (long long)tcur * ROWS;
        const long long eg = ebase + g;
        const bool valid = (eg < E);
        const float* Xrow = pairBuf + slot * SLOT + g * XPITCH;

        long long nd = 0;
        if (valid) {
            if (ebase + ROWS <= E)
                nd = is64 ? NsmP[slot * ROWS + g]
                          : (long long)NsmP32[slot * ROWS * 2 + g];
            else
                nd = is64 ? ((const long long*)index)[eg]
                          : (long long)((const int*)index)[eg];
        }

        // ---- load + convert A; keep bf16 (both patches) + fp32 of patch h ----
        unsigned int ap0[4], ap1[4], ap2[4], ap3[4];
        float2 Fh_lo[4], Fh_hi[4];
        #pragma unroll
        for (int ks = 0; ks < 4; ks++) {
            const int kb = ks * 16 + q * 2;
            float2 f0 = *reinterpret_cast<const float2*>(Xrow + kb);
            float2 f1 = *reinterpret_cast<const float2*>(Xrow + 64 + kb);
            float2 f2 = *reinterpret_cast<const float2*>(Xrow + kb + 8);
            float2 f3 = *reinterpret_cast<const float2*>(Xrow + 64 + kb + 8);
            ap0[ks] = pack_bf16x2(f0.x, f0.y);
            ap1[ks] = pack_bf16x2(f1.x, f1.y);
            ap2[ks] = pack_bf16x2(f2.x, f2.y);
            ap3[ks] = pack_bf16x2(f3.x, f3.y);
            Fh_lo[ks] = h ? f1 : f0;
            Fh_hi[ks] = h ? f3 : f2;
        }

        float* nrow = out + nd * 128 + h * 64;

        // ---- two N-passes: MMA (4 m) -> epilogue -> quad-shuffle -> RED.v4 ----
        #pragma unroll
        for (int pass = 0; pass < 2; pass++) {
            float acc[4][4];
            #pragma unroll
            for (int j = 0; j < 4; j++) {
                acc[j][0] = 0.f; acc[j][1] = 0.f; acc[j][2] = 0.f; acc[j][3] = 0.f;
            }
            #pragma unroll
            for (int ks = 0; ks < 4; ks++) {
                #pragma unroll
                for (int j = 0; j < 4; j++) {
                    const int m = pass * 4 + j;
                    asm volatile(
                        "mma.sync.aligned.m16n8k16.row.col.f32.bf16.bf16.f32 "
                        "{%0,%1,%2,%3}, {%4,%5,%6,%7}, {%8,%9}, {%0,%1,%2,%3};"
                        : "+f"(acc[j][0]), "+f"(acc[j][1]),
                          "+f"(acc[j][2]), "+f"(acc[j][3])
                        : "r"(ap0[ks]), "r"(ap1[ks]), "r"(ap2[ks]), "r"(ap3[ks]),
                          "r"(Breg[m][ks][0]), "r"(Breg[m][ks][1]));
                }
            }
            float2 V[4];
            #pragma unroll
            for (int j = 0; j < 4; j++) {
                const int m  = pass * 4 + j;
                const int ks = m >> 1;
                float2 eh = (m & 1) ? Fh_hi[ks] : Fh_lo[ks];
                unsigned int u0 = (m & 1) ? ap2[ks] : ap0[ks];
                unsigned int u1 = (m & 1) ? ap3[ks] : ap1[ks];
                float2 ge0 = h ? unpack_bf16x2(u0) : eh;
                float2 ge1 = h ? eh : unpack_bf16x2(u1);
                float sx = ge0.x * __saturatef(acc[j][0]) + ge1.x * __saturatef(acc[j][2]);
                float sy = ge0.y * __saturatef(acc[j][1]) + ge1.y * __saturatef(acc[j][3]);
                V[j].x = fmaf(lp, sx, eh.x);
                V[j].y = fmaf(lp, sy, eh.y);
            }
            #pragma unroll
            for (int t2 = 0; t2 < 2; t2++) {
                const int j0 = 2 * t2, j1 = 2 * t2 + 1;
                float2 mine = (q & 1) ? V[j0] : V[j1];
                float ox = __shfl_xor_sync(0xffffffffu, mine.x, 1);
                float oy = __shfl_xor_sync(0xffffffffu, mine.y, 1);
                float2 keep = (q & 1) ? V[j1] : V[j0];
                float vx0 = (q & 1) ? ox : keep.x;
                float vy0 = (q & 1) ? oy : keep.y;
                float vx1 = (q & 1) ? keep.x : ox;
                float vy1 = (q & 1) ? keep.y : oy;
                const int mm = pass * 4 + j0 + (q & 1);   // row this thread reduces
                const int cb = mm * 8 + (q >> 1) * 4;     // col base within half
                if (valid) {
                    asm volatile("red.global.add.v4.f32 [%0], {%1,%2,%3,%4};"
                                 :: "l"(nrow + cb), "f"(vx0), "f"(vy0), "f"(vx1), "f"(vy1)
                                 : "memory");
                }
            }
        }
    }
}

// ---------------- launch ----------------
extern "C" void kernel_launch(void* const* d_in, const int* in_sizes, int n_in,
                              void* d_out, int out_size) {
    const float* x   = (const float*)d_in[0];
    const float* Wg  = (const float*)d_in[1];
    const float* lp  = (const float*)d_in[2];
    const void*  idx = d_in[3];

    long long E = (long long)in_sizes[0] / 128;
    int tiles = (int)((E + ROWS - 1) / ROWS);

    int dev = 0; cudaGetDevice(&dev);
    int sms = 148;
    cudaDeviceGetAttribute(&sms, cudaDevAttrMultiProcessorCount, dev);

    // prep: zero output + detect index dtype (single launch)
    int n4 = out_size / 4;
    long long npairs64 = E / 2; int npairs = npairs64 > 4096 ? 4096 : (int)npairs64;
    int zgrid = (n4 + 255) / 256;
    prep_kernel<<<zgrid, 256>>>((float4*)d_out, n4, (const unsigned int*)idx, npairs);

    size_t smem = (size_t)PAIRS * NBUF * SLOT * 4       // X rings
                + (size_t)PAIRS * NBUF * ROWS * 8;      // node rings
    cudaFuncSetAttribute(fused_gate_scatter,
                         cudaFuncAttributeMaxDynamicSharedMemorySize, (int)smem);
    int grid = 4 * sms;
    int maxg = (tiles + PAIRS - 1) / PAIRS;
    if (grid > maxg) grid = maxg;
    fused_gate_scatter<<<grid, THREADS, smem>>>(x, Wg, lp, idx, (float*)d_out, E, tiles);
}